// round 2
// baseline (speedup 1.0000x reference)
#include <cuda_runtime.h>
#include <cstdint>

// 2D acoustic FDTD, 500 steps, 8 shots, 256x256, 128 recs/shot.
// One persistent kernel; shot = 8-CTA cluster; field in SMEM+registers.
// p2p neighbor mbarrier sync (no cluster.sync in the loop).

#define DT 0.001f
#define DX 10.0f

constexpr int NT   = 500;
constexpr int NS   = 8;
constexpr int NZ   = 256;
constexpr int NXC  = 256;
constexpr int NREC = 128;

constexpr int CSZ  = 8;
constexpr int ROWS = NZ / CSZ;          // 32
constexpr int NTHREADS = 512;
constexpr int COL4 = NXC / 4;           // 64
constexpr int RG   = NTHREADS / COL4;   // 8
constexpr int RPT  = ROWS / RG;         // 4

constexpr int BUF_ELEMS = ROWS * NXC;   // 8192
constexpr size_t SMEM_BYTES = (size_t)(2 * BUF_ELEMS + 512) * sizeof(float);

// ---------------------------------------------------------------- PTX helpers
__device__ __forceinline__ uint32_t cvta_smem(const void* p) {
    return (uint32_t)__cvta_generic_to_shared(p);
}
__device__ __forceinline__ uint32_t mapa_cluster(uint32_t laddr, uint32_t rank) {
    uint32_t r;
    asm("mapa.shared::cluster.u32 %0, %1, %2;" : "=r"(r) : "r"(laddr), "r"(rank));
    return r;
}
__device__ __forceinline__ float4 ld_dsmem_v4(uint32_t addr) {
    float4 v;
    asm volatile("ld.shared::cluster.v4.f32 {%0,%1,%2,%3}, [%4];"
                 : "=f"(v.x), "=f"(v.y), "=f"(v.z), "=f"(v.w) : "r"(addr));
    return v;
}
__device__ __forceinline__ void cluster_sync_() {
    asm volatile("barrier.cluster.arrive.aligned;" ::: "memory");
    asm volatile("barrier.cluster.wait.aligned;" ::: "memory");
}
__device__ __forceinline__ uint32_t cluster_rank_() {
    uint32_t r;
    asm("mov.u32 %0, %%cluster_ctarank;" : "=r"(r));
    return r;
}
__device__ __forceinline__ void mbar_init(uint32_t addr, uint32_t count) {
    asm volatile("mbarrier.init.shared.b64 [%0], %1;" :: "r"(addr), "r"(count) : "memory");
}
__device__ __forceinline__ void mbar_arrive_remote(uint32_t addr) {
    asm volatile("mbarrier.arrive.release.cluster.shared::cluster.b64 _, [%0];"
                 :: "r"(addr) : "memory");
}
__device__ __forceinline__ void mbar_wait(uint32_t addr, uint32_t parity) {
    asm volatile(
        "{\n\t"
        ".reg .pred P;\n\t"
        "WL%=:\n\t"
        "mbarrier.try_wait.parity.acquire.cluster.shared::cta.b64 P, [%0], %1, 0x989680;\n\t"
        "@!P bra WL%=;\n\t"
        "}"
        :: "r"(addr), "r"(parity) : "memory");
}

// ---------------------------------------------------------------- kernel
__global__ void __cluster_dims__(CSZ, 1, 1) __launch_bounds__(NTHREADS, 1)
wave_kernel(const float* __restrict__ x,     // (NT, NS)
            const float* __restrict__ vp,    // (NZ, NXC)
            const int*   __restrict__ src,   // (NS, 2)
            const int*   __restrict__ rec,   // (NS, NREC, 2)
            float*       __restrict__ out)   // (NT, NS, NREC)
{
    extern __shared__ float sm[];
    float* buf0 = sm;
    float* buf1 = sm + BUF_ELEMS;
    float* xs   = sm + 2 * BUF_ELEMS;
    float* bufs[2] = { buf0, buf1 };

    __shared__ uint64_t bar_n, bar_s;     // arrivals from north / south neighbor
    __shared__ int rcnt;
    __shared__ int2 rlist[NREC];

    const int tid  = threadIdx.x;
    const uint32_t rank = cluster_rank_();
    const int shot = blockIdx.x / CSZ;

    const int col4 = tid & (COL4 - 1);
    const int rg   = tid >> 6;
    const int lr0  = rg * RPT;
    const int xcol = col4 * 4;
    const int lane = tid & 31;
    const bool has_n = (rank > 0);
    const bool has_s = (rank < CSZ - 1);

    // --- init ----------------------------------------------------------------
    for (int i = tid; i < BUF_ELEMS; i += NTHREADS) { buf0[i] = 0.f; buf1[i] = 0.f; }
    for (int i = tid; i < NT; i += NTHREADS) xs[i] = x[i * NS + shot];
    if (tid == 0) {
        mbar_init(cvta_smem(&bar_n), 1);
        mbar_init(cvta_smem(&bar_s), 1);
        rcnt = 0;
    }
    __syncthreads();

    // claim receivers owned by this CTA (rz in [rank*ROWS, (rank+1)*ROWS))
    if (tid < NREC) {
        const int gi = shot * NREC + tid;
        const int rz = rec[gi * 2 + 0];
        const int rx = rec[gi * 2 + 1];
        if ((uint32_t)(rz >> 5) == rank) {
            int s = atomicAdd(&rcnt, 1);
            rlist[s] = make_int2((rz & 31) * NXC + rx, shot * NREC + tid);
        }
    }

    // c2 in registers
    float4 c2r[RPT];
    const float sc = DT / DX;
#pragma unroll
    for (int j = 0; j < RPT; j++) {
        const int g = (int)rank * ROWS + lr0 + j;
        float4 v = *(const float4*)(vp + g * NXC + xcol);
        float a = v.x * sc, b = v.y * sc, c = v.z * sc, d = v.w * sc;
        c2r[j] = make_float4(a * a, b * b, c * c, d * d);
    }

    // field registers: prev and cur (both zero at t=0)
    float4 pr[RPT], cC[RPT];
#pragma unroll
    for (int j = 0; j < RPT; j++) {
        pr[j] = make_float4(0.f, 0.f, 0.f, 0.f);
        cC[j] = make_float4(0.f, 0.f, 0.f, 0.f);
    }

    // source ownership
    const int sz = src[shot * 2 + 0];
    const int sx = src[shot * 2 + 1];
    const int sj = sz - ((int)rank * ROWS + lr0);
    const bool shere = (sj >= 0 && sj < RPT && sx >= xcol && sx < xcol + 4);
    const int scomp = sx - xcol;

    // DSMEM halo addresses (both parities)
    const uint32_t sa0 = cvta_smem(buf0);
    const uint32_t sa1 = cvta_smem(buf1);
    uint32_t nh_addr[2] = {0, 0}, sh_addr[2] = {0, 0};
    if (rg == 0 && has_n) {
        const uint32_t off = (uint32_t)((ROWS - 1) * NXC + xcol) * 4u;
        nh_addr[0] = mapa_cluster(sa0 + off, rank - 1);
        nh_addr[1] = mapa_cluster(sa1 + off, rank - 1);
    }
    if (rg == RG - 1 && has_s) {
        const uint32_t off = (uint32_t)(xcol) * 4u;
        sh_addr[0] = mapa_cluster(sa0 + off, rank + 1);
        sh_addr[1] = mapa_cluster(sa1 + off, rank + 1);
    }

    // remote arrive addresses: I signal north's bar_s and south's bar_n
    uint32_t arr_n = 0, arr_s = 0;
    if (tid == 0) {
        if (has_n) arr_n = mapa_cluster(cvta_smem(&bar_s), rank - 1);
        if (has_s) arr_s = mapa_cluster(cvta_smem(&bar_n), rank + 1);
    }

    __syncthreads();
    // my receiver assignment (registers)
    const bool samp = (tid < rcnt);
    int roff = 0, rout = 0;
    if (samp) { int2 e = rlist[tid]; roff = e.x; rout = e.y; }

    const uint32_t ba_n = cvta_smem(&bar_n);
    const uint32_t ba_s = cvta_smem(&bar_s);

    cluster_sync_();  // buffers zeroed + mbarriers initialized cluster-wide

    // --- main time loop ------------------------------------------------------
    int p = 0;
    for (int t = 0; t < NT; t++) {
        const float* cur = bufs[p];
        float*       nxt = bufs[p ^ 1];
        int toff = t + 2; if (toff > NT - 1) toff = NT - 1;
        const float amp = xs[t] + xs[toff];

        // boundary warps wait for neighbor's previous-step completion
        if (t > 0) {
            const uint32_t par = (uint32_t)((t - 1) & 1);
            if (rg == 0 && has_n)      mbar_wait(ba_n, par);
            if (rg == RG - 1 && has_s) mbar_wait(ba_s, par);
        }

        // north value for first row of strip
        float4 cN;
        if (rg == 0) {
            cN = has_n ? ld_dsmem_v4(nh_addr[p]) : make_float4(0.f, 0.f, 0.f, 0.f);
        } else {
            cN = *(const float4*)(cur + (lr0 - 1) * NXC + xcol);
        }

#pragma unroll
        for (int j = 0; j < RPT; j++) {
            const int lr = lr0 + j;
            const float4 cc = cC[j];

            float4 cS;
            if (j < RPT - 1) {
                cS = cC[j + 1];
            } else if (rg == RG - 1) {
                cS = has_s ? ld_dsmem_v4(sh_addr[p]) : make_float4(0.f, 0.f, 0.f, 0.f);
            } else {
                cS = *(const float4*)(cur + (lr + 1) * NXC + xcol);
            }

            // horizontal neighbors: lane shuffles, warp-edge lanes hit smem
            float lft = __shfl_up_sync(0xffffffffu, cc.w, 1);
            float rgt = __shfl_down_sync(0xffffffffu, cc.x, 1);
            if (lane == 0)  lft = (col4 == 0)        ? 0.f : cur[lr * NXC + xcol - 1];
            if (lane == 31) rgt = (col4 == COL4 - 1) ? 0.f : cur[lr * NXC + xcol + 4];

            float4 lap;
            lap.x = cN.x + cS.x + lft  + cc.y - 4.f * cc.x;
            lap.y = cN.y + cS.y + cc.x + cc.z - 4.f * cc.y;
            lap.z = cN.z + cS.z + cc.y + cc.w - 4.f * cc.z;
            lap.w = cN.w + cS.w + cc.z + rgt  - 4.f * cc.w;

            float4 nv;
            nv.x = 2.f * cc.x - pr[j].x + c2r[j].x * lap.x;
            nv.y = 2.f * cc.y - pr[j].y + c2r[j].y * lap.y;
            nv.z = 2.f * cc.z - pr[j].z + c2r[j].z * lap.z;
            nv.w = 2.f * cc.w - pr[j].w + c2r[j].w * lap.w;

            if (shere && j == sj) {
                if      (scomp == 0) nv.x += amp;
                else if (scomp == 1) nv.y += amp;
                else if (scomp == 2) nv.z += amp;
                else                 nv.w += amp;
            }

            *(float4*)(nxt + lr * NXC + xcol) = nv;
            pr[j] = cc;
            cC[j] = nv;
            cN = cc;
        }

        __syncthreads();   // CTA-wide: all nxt stores visible (drains STS)

        // signal neighbors: my step t is fully published
        if (tid == 0) {
            if (has_n) mbar_arrive_remote(arr_n);
            if (has_s) mbar_arrive_remote(arr_s);
        }

        // owner-local receiver sampling from the freshly written buffer
        if (samp) {
            out[t * (NS * NREC) + rout] = nxt[roff];
        }

        p ^= 1;
    }

    cluster_sync_();  // keep cluster smem alive until all CTAs are done
}

// ---------------------------------------------------------------- launch
extern "C" void kernel_launch(void* const* d_in, const int* in_sizes, int n_in,
                              void* d_out, int out_size)
{
    const float* x   = (const float*)d_in[0];
    const float* vp  = (const float*)d_in[1];
    const int*   src = (const int*)d_in[2];
    const int*   rec = (const int*)d_in[3];
    float*       out = (float*)d_out;

    cudaFuncSetAttribute((const void*)wave_kernel,
                         cudaFuncAttributeMaxDynamicSharedMemorySize,
                         (int)SMEM_BYTES);

    wave_kernel<<<NS * CSZ, NTHREADS, SMEM_BYTES>>>(x, vp, src, rec, out);
}

// round 4
// speedup vs baseline: 1.2197x; 1.2197x over previous
#include <cuda_runtime.h>
#include <cstdint>

// 2D acoustic FDTD, 500 steps, 8 shots, 256x256, 128 recs/shot.
// One persistent kernel; shot = 8-CTA cluster; fields in SMEM.
// 1024 threads/CTA, one cluster.sync per step, owner-local receivers.

#define DT 0.001f
#define DX 10.0f

constexpr int NT   = 500;
constexpr int NS   = 8;
constexpr int NZ   = 256;
constexpr int NXC  = 256;
constexpr int NREC = 128;

constexpr int CSZ  = 8;
constexpr int ROWS = NZ / CSZ;          // 32
constexpr int NTHREADS = 1024;
constexpr int COL4 = NXC / 4;           // 64
constexpr int RG   = NTHREADS / COL4;   // 16 row-groups
constexpr int RPT  = ROWS / RG;         // 2 rows per thread

constexpr int BUF_ELEMS = ROWS * NXC;   // 8192
constexpr size_t SMEM_BYTES = (size_t)(2 * BUF_ELEMS + 512) * sizeof(float);

// ---------------------------------------------------------------- PTX helpers
__device__ __forceinline__ uint32_t cvta_smem(const void* p) {
    return (uint32_t)__cvta_generic_to_shared(p);
}
__device__ __forceinline__ uint32_t mapa_cluster(uint32_t laddr, uint32_t rank) {
    uint32_t r;
    asm("mapa.shared::cluster.u32 %0, %1, %2;" : "=r"(r) : "r"(laddr), "r"(rank));
    return r;
}
__device__ __forceinline__ float4 ld_dsmem_v4(uint32_t addr) {
    float4 v;
    asm volatile("ld.shared::cluster.v4.f32 {%0,%1,%2,%3}, [%4];"
                 : "=f"(v.x), "=f"(v.y), "=f"(v.z), "=f"(v.w) : "r"(addr));
    return v;
}
__device__ __forceinline__ void cluster_sync_() {
    asm volatile("barrier.cluster.arrive.aligned;" ::: "memory");
    asm volatile("barrier.cluster.wait.aligned;" ::: "memory");
}
__device__ __forceinline__ uint32_t cluster_rank_() {
    uint32_t r;
    asm("mov.u32 %0, %%cluster_ctarank;" : "=r"(r));
    return r;
}

// ---------------------------------------------------------------- kernel
__global__ void __cluster_dims__(CSZ, 1, 1) __launch_bounds__(NTHREADS, 1)
wave_kernel(const float* __restrict__ x,     // (NT, NS)
            const float* __restrict__ vp,    // (NZ, NXC)
            const int*   __restrict__ src,   // (NS, 2)
            const int*   __restrict__ rec,   // (NS, NREC, 2)
            float*       __restrict__ out)   // (NT, NS, NREC)
{
    extern __shared__ float sm[];
    float* buf0 = sm;
    float* buf1 = sm + BUF_ELEMS;
    float* xs   = sm + 2 * BUF_ELEMS;

    __shared__ int rcnt;
    __shared__ int2 rlist[NREC];

    const int tid  = threadIdx.x;
    const uint32_t rank = cluster_rank_();
    const int shot = blockIdx.x / CSZ;

    const int col4 = tid & (COL4 - 1);
    const int rg   = tid >> 6;           // 0..15
    const int lr0  = rg * RPT;           // 2*rg
    const int xcol = col4 * 4;
    const bool has_n = (rank > 0);
    const bool has_s = (rank < CSZ - 1);

    // --- init ----------------------------------------------------------------
    for (int i = tid; i < BUF_ELEMS; i += NTHREADS) { buf0[i] = 0.f; buf1[i] = 0.f; }
    for (int i = tid; i < NT; i += NTHREADS) xs[i] = x[i * NS + shot];
    if (tid == 0) rcnt = 0;
    __syncthreads();

    // claim receivers owned by this CTA (rz in [rank*ROWS, (rank+1)*ROWS))
    if (tid < NREC) {
        const int gi = shot * NREC + tid;
        const int rz = rec[gi * 2 + 0];
        const int rx = rec[gi * 2 + 1];
        if ((uint32_t)(rz >> 5) == rank) {
            int s = atomicAdd(&rcnt, 1);
            rlist[s] = make_int2((rz & 31) * NXC + rx, shot * NREC + tid);
        }
    }

    // c2 in registers
    float4 c2r[RPT];
    const float sc = DT / DX;
#pragma unroll
    for (int j = 0; j < RPT; j++) {
        const int g = (int)rank * ROWS + lr0 + j;
        float4 v = *(const float4*)(vp + g * NXC + xcol);
        float a = v.x * sc, b = v.y * sc, c = v.z * sc, d = v.w * sc;
        c2r[j] = make_float4(a * a, b * b, c * c, d * d);
    }

    // prev in registers (zero at t=0)
    float4 pr[RPT];
#pragma unroll
    for (int j = 0; j < RPT; j++) pr[j] = make_float4(0.f, 0.f, 0.f, 0.f);

    // source ownership
    const int sz = src[shot * 2 + 0];
    const int sx = src[shot * 2 + 1];
    const int sj = sz - ((int)rank * ROWS + lr0);
    const bool shere = (sj >= 0 && sj < RPT && sx >= xcol && sx < xcol + 4);
    const int scomp = sx - xcol;

    // DSMEM halo addresses (both parities)
    const uint32_t sa0 = cvta_smem(buf0);
    const uint32_t sa1 = cvta_smem(buf1);
    uint32_t nh_addr[2] = {0, 0}, sh_addr[2] = {0, 0};
    if (rg == 0 && has_n) {
        const uint32_t off = (uint32_t)((ROWS - 1) * NXC + xcol) * 4u;
        nh_addr[0] = mapa_cluster(sa0 + off, rank - 1);
        nh_addr[1] = mapa_cluster(sa1 + off, rank - 1);
    }
    if (rg == RG - 1 && has_s) {
        const uint32_t off = (uint32_t)(xcol) * 4u;
        sh_addr[0] = mapa_cluster(sa0 + off, rank + 1);
        sh_addr[1] = mapa_cluster(sa1 + off, rank + 1);
    }

    __syncthreads();
    const bool samp = (tid < rcnt);
    int roff = 0;
    float* outp = out;
    if (samp) {
        int2 e = rlist[tid];
        roff = e.x;
        outp = out + e.y;
    }

    cluster_sync_();  // zeroed buffers visible cluster-wide

    // --- main time loop ------------------------------------------------------
    int p = 0;
    for (int t = 0; t < NT; t++) {
        const float* cur = p ? buf1 : buf0;
        float*       nxt = p ? buf0 : buf1;
        const int toff = (t + 2 < NT - 1) ? t + 2 : NT - 1;
        const float amp = xs[t] + xs[toff];

        // north value for first row of strip
        float4 cN;
        if (rg == 0) {
            cN = has_n ? ld_dsmem_v4(nh_addr[p]) : make_float4(0.f, 0.f, 0.f, 0.f);
        } else {
            cN = *(const float4*)(cur + (lr0 - 1) * NXC + xcol);
        }
        float4 cC = *(const float4*)(cur + lr0 * NXC + xcol);

#pragma unroll
        for (int j = 0; j < RPT; j++) {
            const int lr = lr0 + j;
            float4 cS;
            if (j == RPT - 1 && rg == RG - 1) {   // lr == ROWS-1
                cS = has_s ? ld_dsmem_v4(sh_addr[p])
                           : make_float4(0.f, 0.f, 0.f, 0.f);
            } else {
                cS = *(const float4*)(cur + (lr + 1) * NXC + xcol);
            }
            const float lft = (xcol > 0)       ? cur[lr * NXC + xcol - 1] : 0.f;
            const float rgt = (xcol + 4 < NXC) ? cur[lr * NXC + xcol + 4] : 0.f;

            float4 lap;
            lap.x = cN.x + cS.x + lft  + cC.y - 4.f * cC.x;
            lap.y = cN.y + cS.y + cC.x + cC.z - 4.f * cC.y;
            lap.z = cN.z + cS.z + cC.y + cC.w - 4.f * cC.z;
            lap.w = cN.w + cS.w + cC.z + rgt  - 4.f * cC.w;

            float4 nv;
            nv.x = 2.f * cC.x - pr[j].x + c2r[j].x * lap.x;
            nv.y = 2.f * cC.y - pr[j].y + c2r[j].y * lap.y;
            nv.z = 2.f * cC.z - pr[j].z + c2r[j].z * lap.z;
            nv.w = 2.f * cC.w - pr[j].w + c2r[j].w * lap.w;

            if (shere && j == sj) {
                if      (scomp == 0) nv.x += amp;
                else if (scomp == 1) nv.y += amp;
                else if (scomp == 2) nv.z += amp;
                else                 nv.w += amp;
            }

            *(float4*)(nxt + lr * NXC + xcol) = nv;
            pr[j] = cC;
            cN = cC;
            cC = cS;
        }

        // one barrier per step: release my stores, acquire everyone's.
        cluster_sync_();

        // owner-local receiver sampling from the freshly written buffer
        if (samp) {
            *outp = nxt[roff];
            outp += NS * NREC;
        }

        p ^= 1;
    }
}

// ---------------------------------------------------------------- launch
extern "C" void kernel_launch(void* const* d_in, const int* in_sizes, int n_in,
                              void* d_out, int out_size)
{
    const float* x   = (const float*)d_in[0];
    const float* vp  = (const float*)d_in[1];
    const int*   src = (const int*)d_in[2];
    const int*   rec = (const int*)d_in[3];
    float*       out = (float*)d_out;

    cudaFuncSetAttribute((const void*)wave_kernel,
                         cudaFuncAttributeMaxDynamicSharedMemorySize,
                         (int)SMEM_BYTES);

    wave_kernel<<<NS * CSZ, NTHREADS, SMEM_BYTES>>>(x, vp, src, rec, out);
}